// round 13
// baseline (speedup 1.0000x reference)
#include <cuda_runtime.h>
#include <cuda_fp16.h>
#include <cstdint>
#include <cstddef>

// ---------------------------------------------------------------------------
// Problem constants
// ---------------------------------------------------------------------------
#define K_DIM 4096
#define N_DIM 4096
#define M_DIM 8192
#define NNZ   262144

// GEMM tiling — fp16 mma.sync, CTA 128x256, warp tile 64x64
#define BM 128
#define BN 256
#define BK 64                      // 64 fp16 = 128 B rows (XOR-swizzled)
#define NK (K_DIM / BK)            // 64 chunks
#define STAGES 4

#define NTHREADS 320               // 8 compute warps + 2 producer warps

// Stage layout (bytes): A (128 rows x 128B) | B (256 rows x 128B)
#define A_OFF 0
#define B_OFF 16384
#define SSIZE 49152
#define DSMEM_BYTES (STAGES * SSIZE + 1024)   // ~193 KB -> 1 CTA/SM

// ---------------------------------------------------------------------------
// Device global scratch (allocation-free rule)
// ---------------------------------------------------------------------------
__device__ __half g_Wh[(size_t)N_DIM * K_DIM];
__device__ __half g_Xh[(size_t)M_DIM * K_DIM];

// ---------------------------------------------------------------------------
// PTX helpers (sm_80-level only: cp.async, ldmatrix, mma.sync, named bars)
// ---------------------------------------------------------------------------
__device__ __forceinline__ uint32_t smem_u32(const void* p) {
    uint32_t a;
    asm("{ .reg .u64 t; cvta.to.shared.u64 t, %1; cvt.u32.u64 %0, t; }"
        : "=r"(a) : "l"(p));
    return a;
}

__device__ __forceinline__ void cp16(uint32_t d, const void* s) {
    asm volatile("cp.async.cg.shared.global [%0], [%1], 16;" :: "r"(d), "l"(s) : "memory");
}
__device__ __forceinline__ void cp_commit() { asm volatile("cp.async.commit_group;" ::: "memory"); }
__device__ __forceinline__ void cp_wait0()  { asm volatile("cp.async.wait_group 0;" ::: "memory"); }

__device__ __forceinline__ void bar_sync(int id) {
    asm volatile("bar.sync %0, %1;" :: "r"(id), "n"(NTHREADS) : "memory");
}
__device__ __forceinline__ void bar_arrive(int id) {
    asm volatile("bar.arrive %0, %1;" :: "r"(id), "n"(NTHREADS) : "memory");
}

#define LDSM4(r, addr)                                                          \
    asm volatile("ldmatrix.sync.aligned.m8n8.x4.shared.b16 {%0,%1,%2,%3}, [%4];" \
                 : "=r"((r)[0]), "=r"((r)[1]), "=r"((r)[2]), "=r"((r)[3])        \
                 : "r"(addr))

#define MMA16816(c, a, b0, b1)                                                  \
    asm volatile("mma.sync.aligned.m16n8k16.row.col.f32.f16.f16.f32 "           \
                 "{%0,%1,%2,%3},{%4,%5,%6,%7},{%8,%9},{%0,%1,%2,%3};"           \
                 : "+f"((c)[0]), "+f"((c)[1]), "+f"((c)[2]), "+f"((c)[3])       \
                 : "r"((a)[0]), "r"((a)[1]), "r"((a)[2]), "r"((a)[3]),          \
                   "r"(b0), "r"(b1))

// ---------------------------------------------------------------------------
// Kernel 1: convert W -> fp16 directly
// ---------------------------------------------------------------------------
__device__ __forceinline__ void h4_store(float4 v, __half* __restrict__ dst, size_t base) {
    __half2 p01 = __floats2half2_rn(v.x, v.y);
    __half2 p23 = __floats2half2_rn(v.z, v.w);
    uint2 u;
    u.x = *reinterpret_cast<uint32_t*>(&p01);
    u.y = *reinterpret_cast<uint32_t*>(&p23);
    *reinterpret_cast<uint2*>(dst + base) = u;
}

__global__ void convert_w_kernel(const float* __restrict__ w) {
    size_t i = (size_t)blockIdx.x * blockDim.x + threadIdx.x;
    const size_t n4 = (size_t)N_DIM * K_DIM / 4;
    if (i < n4) {
        float4 v = reinterpret_cast<const float4*>(w)[i];
        h4_store(v, g_Wh, i * 4);
    }
}

// ---------------------------------------------------------------------------
// Kernel 2: scatter shira delta into fp16 weight (half atomics)
// ---------------------------------------------------------------------------
__global__ void scatter_delta_kernel(const float* __restrict__ sw, const int* __restrict__ idx) {
    int i = blockIdx.x * blockDim.x + threadIdx.x;
    if (i < NNZ) {
        int r = idx[i];
        int c = idx[NNZ + i];
        atomicAdd(&g_Wh[(size_t)r * K_DIM + c], __float2half(sw[i]));
    }
}

// ---------------------------------------------------------------------------
// Kernel 3: convert x -> fp16
// ---------------------------------------------------------------------------
__global__ void convert_x_kernel(const float* __restrict__ x) {
    size_t i = (size_t)blockIdx.x * blockDim.x + threadIdx.x;
    const size_t n4 = (size_t)M_DIM * K_DIM / 4;
    if (i < n4) {
        float4 v = reinterpret_cast<const float4*>(x)[i];
        h4_store(v, g_Xh, i * 4);
    }
}

// ---------------------------------------------------------------------------
// Kernel 4: warp-specialized fp16 GEMM.
//   warps 0-7: compute (64x64 tiles). warps 8-9: cp.async producer.
// Named barriers: full[s] = 1+s (producer arrives, consumers sync),
//                 empty[s] = 5+s (consumers arrive, producer syncs).
// ---------------------------------------------------------------------------
extern __shared__ char dsm[];

__global__ void __launch_bounds__(NTHREADS, 1)
gemm_fp16_ws_kernel(const float* __restrict__ bias, float* __restrict__ out) {
    const int tid  = threadIdx.x;
    const int wid  = tid >> 5;
    const int lane = tid & 31;

    const int m0 = blockIdx.y * BM;
    const int n0 = blockIdx.x * BN;

    uint32_t sb = (smem_u32(dsm) + 1023u) & ~1023u;

    if (wid >= 8) {
        // ---------------- producer: 2 warps, 64 threads ----------------
        const int ptid = tid - 256;            // 0..63
        const char* pA = (const char*)g_Xh + (size_t)m0 * (K_DIM * 2);
        const char* pB = (const char*)g_Wh + (size_t)n0 * (K_DIM * 2);

        for (int kt = 0; kt < NK; ++kt) {
            if (kt >= STAGES) bar_sync(5 + (kt & 3));   // wait slot consumed
            const uint32_t st = sb + (kt & 3) * SSIZE;
            const size_t koff = (size_t)kt * 128;
#pragma unroll
            for (int j = 0; j < 16; ++j) {             // A: 1024 cp16 / 64 thr
                int o  = j * 64 + ptid;
                int r  = o >> 3;
                int sg = o & 7;
                size_t go = (size_t)r * (K_DIM * 2) + koff + (size_t)sg * 16;
                uint32_t so = (uint32_t)(r * 128) + (uint32_t)((sg * 16) ^ ((r & 7) << 4));
                cp16(st + A_OFF + so, pA + go);
            }
#pragma unroll
            for (int j = 0; j < 32; ++j) {             // B: 2048 cp16 / 64 thr
                int o  = j * 64 + ptid;
                int r  = o >> 3;
                int sg = o & 7;
                size_t go = (size_t)r * (K_DIM * 2) + koff + (size_t)sg * 16;
                uint32_t so = (uint32_t)(r * 128) + (uint32_t)((sg * 16) ^ ((r & 7) << 4));
                cp16(st + B_OFF + so, pB + go);
            }
            cp_commit();
            cp_wait0();                                 // this chunk landed
            bar_arrive(1 + (kt & 3));                   // publish full
        }
        return;
    }

    // ---------------- compute: 8 warps ----------------
    const int wm = wid & 1;        // 2 M-slots of 64 rows
    const int wn = wid >> 1;       // 4 N-slots of 64 cols

    float acc[4][8][4];
#pragma unroll
    for (int i = 0; i < 4; ++i)
#pragma unroll
        for (int j = 0; j < 8; ++j)
#pragma unroll
            for (int q = 0; q < 4; ++q) acc[i][j][q] = 0.0f;

    // Per-lane ldmatrix addressing (tile row = base + (lane&15); row&7 == lane&7,
    // so the XOR swizzle term is a per-lane constant folded into xks[]).
    const int l15 = lane & 15;
    const int lhi = lane >> 4;
    const uint32_t lsw = (uint32_t)((lane & 7) << 4);
    uint32_t xks[4];
#pragma unroll
    for (int ks = 0; ks < 4; ++ks)
        xks[ks] = (uint32_t)(ks * 32 + lhi * 16) ^ lsw;

    const uint32_t aRow = (uint32_t)((wm * 64 + l15) * 128);
    const uint32_t bRow = (uint32_t)((wn * 64 + l15) * 128);

    uint32_t aF[2][16], bF[2][16];

#define LOAD_FRAGS(buf, slot, ks)                                               \
    do {                                                                        \
        _Pragma("unroll")                                                       \
        for (int mi = 0; mi < 4; ++mi)                                          \
            LDSM4(aF[buf] + mi * 4,                                             \
                  (slot) + A_OFF + aRow + (uint32_t)(mi * 2048) + xks[ks]);     \
        _Pragma("unroll")                                                       \
        for (int nb = 0; nb < 4; ++nb)                                          \
            LDSM4(bF[buf] + nb * 4,                                             \
                  (slot) + B_OFF + bRow + (uint32_t)(nb * 2048) + xks[ks]);     \
    } while (0)

#define DO_MMAS(buf)                                                            \
    do {                                                                        \
        _Pragma("unroll")                                                       \
        for (int mi = 0; mi < 4; ++mi) {                                        \
            _Pragma("unroll")                                                   \
            for (int j = 0; j < 8; ++j) {                                       \
                const int g = j >> 1, s = j & 1;                                \
                MMA16816(acc[mi][j], aF[buf] + mi * 4,                          \
                         bF[buf][g * 4 + s], bF[buf][g * 4 + 2 + s]);           \
            }                                                                   \
        }                                                                       \
    } while (0)

    for (int kt = 0; kt < NK; ++kt) {
        bar_sync(1 + (kt & 3));                         // wait slot full
        const uint32_t slot = sb + (kt & 3) * SSIZE;

        // Software-pipelined k-steps: LDSM(ks+1) before MMA(ks)
        LOAD_FRAGS(0, slot, 0);
        LOAD_FRAGS(1, slot, 1);
        DO_MMAS(0);
        LOAD_FRAGS(0, slot, 2);
        DO_MMAS(1);
        LOAD_FRAGS(1, slot, 3);
        DO_MMAS(0);
        DO_MMAS(1);

        bar_arrive(5 + (kt & 3));                       // MMAs consumed frags
    }

    // Epilogue: C frag (m16n8): c0,c1 at (m = l>>2, n = 2*(l&3)); c2,c3 at m+8.
    const int mBase = m0 + wm * 64;
    const int nBase = n0 + wn * 64;
    const int rsub  = lane >> 2;
    const int csub  = (lane & 3) * 2;
#pragma unroll
    for (int j = 0; j < 8; ++j) {
        const int n = nBase + j * 8 + csub;
        const float2 b2 = *reinterpret_cast<const float2*>(bias + n);
#pragma unroll
        for (int mi = 0; mi < 4; ++mi) {
            const int r0 = mBase + mi * 16 + rsub;
            float2 v0, v1;
            v0.x = acc[mi][j][0] + b2.x;
            v0.y = acc[mi][j][1] + b2.y;
            v1.x = acc[mi][j][2] + b2.x;
            v1.y = acc[mi][j][3] + b2.y;
            *reinterpret_cast<float2*>(out + (size_t)r0 * N_DIM + n)       = v0;
            *reinterpret_cast<float2*>(out + (size_t)(r0 + 8) * N_DIM + n) = v1;
        }
    }
}

// ---------------------------------------------------------------------------
// Entry point
// ---------------------------------------------------------------------------
extern "C" void kernel_launch(void* const* d_in, const int* in_sizes, int n_in,
                              void* d_out, int out_size) {
    const float* x    = (const float*)d_in[0];   // [4, 2048, 4096]
    const float* w    = (const float*)d_in[1];   // [4096, 4096]
    const float* bias = (const float*)d_in[2];   // [4096]
    const float* sw   = (const float*)d_in[3];   // [262144]
    const int*   idx  = (const int*)d_in[4];     // [2, 262144]
    float* out = (float*)d_out;                  // [8192, 4096]

    {
        const size_t n4 = (size_t)N_DIM * K_DIM / 4;
        convert_w_kernel<<<(int)((n4 + 255) / 256), 256>>>(w);
    }
    scatter_delta_kernel<<<(NNZ + 255) / 256, 256>>>(sw, idx);
    {
        const size_t n4 = (size_t)M_DIM * K_DIM / 4;
        convert_x_kernel<<<(int)((n4 + 255) / 256), 256>>>(x);
    }
    {
        cudaFuncSetAttribute(gemm_fp16_ws_kernel,
                             cudaFuncAttributeMaxDynamicSharedMemorySize, DSMEM_BYTES);
        dim3 grid(N_DIM / BN, M_DIM / BM);   // (16, 64)
        gemm_fp16_ws_kernel<<<grid, NTHREADS, DSMEM_BYTES>>>(bias, out);
    }
}

// round 14
// speedup vs baseline: 1.1194x; 1.1194x over previous
#include <cuda_runtime.h>
#include <cuda_fp16.h>
#include <cstdint>
#include <cstddef>

// ---------------------------------------------------------------------------
// Problem constants
// ---------------------------------------------------------------------------
#define K_DIM 4096
#define N_DIM 4096
#define M_DIM 8192
#define NNZ   262144

// GEMM tiling — fp16 mma.sync, CTA 128x128, 4 warps (2x2), warp tile 64x64
#define BM 128
#define BN 128
#define BK 64                      // 64 fp16 = 128 B rows (XOR-swizzled)
#define NK (K_DIM / BK)            // 64 chunks
#define STAGES 3

// Stage layout (bytes): A (128 rows x 128B) | B (128 rows x 128B)
#define A_OFF 0
#define B_OFF 16384
#define SSIZE 32768
#define DSMEM_BYTES (STAGES * SSIZE + 1024)   // ~97 KB -> 2 CTAs/SM

// ---------------------------------------------------------------------------
// Device global scratch (allocation-free rule)
// ---------------------------------------------------------------------------
__device__ __half g_Wh[(size_t)N_DIM * K_DIM];
__device__ __half g_Xh[(size_t)M_DIM * K_DIM];

// ---------------------------------------------------------------------------
// PTX helpers (sm_80-level only: cp.async, ldmatrix, mma.sync)
// ---------------------------------------------------------------------------
__device__ __forceinline__ uint32_t smem_u32(const void* p) {
    uint32_t a;
    asm("{ .reg .u64 t; cvta.to.shared.u64 t, %1; cvt.u32.u64 %0, t; }"
        : "=r"(a) : "l"(p));
    return a;
}

__device__ __forceinline__ void cp16(uint32_t d, const void* s) {
    asm volatile("cp.async.cg.shared.global [%0], [%1], 16;" :: "r"(d), "l"(s) : "memory");
}
__device__ __forceinline__ void cp_commit() { asm volatile("cp.async.commit_group;" ::: "memory"); }
__device__ __forceinline__ void cp_wait1()  { asm volatile("cp.async.wait_group 1;" ::: "memory"); }
__device__ __forceinline__ void cp_wait0()  { asm volatile("cp.async.wait_group 0;" ::: "memory"); }

#define LDSM4(r, addr)                                                          \
    asm volatile("ldmatrix.sync.aligned.m8n8.x4.shared.b16 {%0,%1,%2,%3}, [%4];" \
                 : "=r"((r)[0]), "=r"((r)[1]), "=r"((r)[2]), "=r"((r)[3])        \
                 : "r"(addr))

#define MMA16816(c, a, b0, b1)                                                  \
    asm volatile("mma.sync.aligned.m16n8k16.row.col.f32.f16.f16.f32 "           \
                 "{%0,%1,%2,%3},{%4,%5,%6,%7},{%8,%9},{%0,%1,%2,%3};"           \
                 : "+f"((c)[0]), "+f"((c)[1]), "+f"((c)[2]), "+f"((c)[3])       \
                 : "r"((a)[0]), "r"((a)[1]), "r"((a)[2]), "r"((a)[3]),          \
                   "r"(b0), "r"(b1))

// ---------------------------------------------------------------------------
// Kernel 1: convert W -> fp16 directly
// ---------------------------------------------------------------------------
__device__ __forceinline__ void h4_store(float4 v, __half* __restrict__ dst, size_t base) {
    __half2 p01 = __floats2half2_rn(v.x, v.y);
    __half2 p23 = __floats2half2_rn(v.z, v.w);
    uint2 u;
    u.x = *reinterpret_cast<uint32_t*>(&p01);
    u.y = *reinterpret_cast<uint32_t*>(&p23);
    *reinterpret_cast<uint2*>(dst + base) = u;
}

__global__ void convert_w_kernel(const float* __restrict__ w) {
    size_t i = (size_t)blockIdx.x * blockDim.x + threadIdx.x;
    const size_t n4 = (size_t)N_DIM * K_DIM / 4;
    if (i < n4) {
        float4 v = reinterpret_cast<const float4*>(w)[i];
        h4_store(v, g_Wh, i * 4);
    }
}

// ---------------------------------------------------------------------------
// Kernel 2: scatter shira delta into fp16 weight (half atomics)
// ---------------------------------------------------------------------------
__global__ void scatter_delta_kernel(const float* __restrict__ sw, const int* __restrict__ idx) {
    int i = blockIdx.x * blockDim.x + threadIdx.x;
    if (i < NNZ) {
        int r = idx[i];
        int c = idx[NNZ + i];
        atomicAdd(&g_Wh[(size_t)r * K_DIM + c], __float2half(sw[i]));
    }
}

// ---------------------------------------------------------------------------
// Kernel 3: convert x -> fp16
// ---------------------------------------------------------------------------
__global__ void convert_x_kernel(const float* __restrict__ x) {
    size_t i = (size_t)blockIdx.x * blockDim.x + threadIdx.x;
    const size_t n4 = (size_t)M_DIM * K_DIM / 4;
    if (i < n4) {
        float4 v = reinterpret_cast<const float4*>(x)[i];
        h4_store(v, g_Xh, i * 4);
    }
}

// ---------------------------------------------------------------------------
// Kernel 4: fp16 GEMM via mma.sync.m16n8k16, fragment double-buffered.
// CTA 128x128, 4 warps (2x2), warp tile 64x64, BK=64, 3-stage cp.async,
// 2 CTAs/SM for cross-CTA latency hiding.
// ---------------------------------------------------------------------------
extern __shared__ char dsm[];

__device__ __forceinline__ void load_stage(uint32_t st, int chunk, int tid,
                                           const char* pA, const char* pB) {
    const size_t koff = (size_t)chunk * 128;   // bytes into each K-major row
#pragma unroll
    for (int j = 0; j < 8; ++j) {              // A: 128 rows x 8 segs = 1024 ops
        int o  = j * 128 + tid;
        int r  = o >> 3;
        int sg = o & 7;
        size_t go = (size_t)r * (K_DIM * 2) + koff + (size_t)sg * 16;
        uint32_t so = (uint32_t)(r * 128) + (uint32_t)((sg * 16) ^ ((r & 7) << 4));
        cp16(st + A_OFF + so, pA + go);
    }
#pragma unroll
    for (int j = 0; j < 8; ++j) {              // B: 128 rows x 8 segs = 1024 ops
        int o  = j * 128 + tid;
        int r  = o >> 3;
        int sg = o & 7;
        size_t go = (size_t)r * (K_DIM * 2) + koff + (size_t)sg * 16;
        uint32_t so = (uint32_t)(r * 128) + (uint32_t)((sg * 16) ^ ((r & 7) << 4));
        cp16(st + B_OFF + so, pB + go);
    }
}

__global__ void __launch_bounds__(128, 2)
gemm_fp16_mma_kernel(const float* __restrict__ bias, float* __restrict__ out) {
    const int tid  = threadIdx.x;
    const int wid  = tid >> 5;
    const int lane = tid & 31;
    const int wm   = wid & 1;       // 2 M-slots of 64 rows
    const int wn   = wid >> 1;      // 2 N-slots of 64 cols

    const int m0 = blockIdx.y * BM;
    const int n0 = blockIdx.x * BN;

    uint32_t sb = (smem_u32(dsm) + 1023u) & ~1023u;

    const char* pA = (const char*)g_Xh + (size_t)m0 * (K_DIM * 2);
    const char* pB = (const char*)g_Wh + (size_t)n0 * (K_DIM * 2);

    float acc[4][8][4];
#pragma unroll
    for (int i = 0; i < 4; ++i)
#pragma unroll
        for (int j = 0; j < 8; ++j)
#pragma unroll
            for (int q = 0; q < 4; ++q) acc[i][j][q] = 0.0f;

    // Per-lane ldmatrix addressing (tile row = base + (lane&15); row&7 == lane&7,
    // so the XOR swizzle term is a per-lane constant folded into xks[]).
    const int l15 = lane & 15;
    const int lhi = lane >> 4;
    const uint32_t lsw = (uint32_t)((lane & 7) << 4);
    uint32_t xks[4];
#pragma unroll
    for (int ks = 0; ks < 4; ++ks)
        xks[ks] = (uint32_t)(ks * 32 + lhi * 16) ^ lsw;

    const uint32_t aRow = (uint32_t)((wm * 64 + l15) * 128);
    const uint32_t bRow = (uint32_t)((wn * 64 + l15) * 128);

    // Prologue: stages 0 and 1 in flight
    load_stage(sb, 0, tid, pA, pB);
    cp_commit();
    load_stage(sb + SSIZE, 1, tid, pA, pB);
    cp_commit();

    uint32_t aF[2][16], bF[2][16];

#define LOAD_FRAGS(buf, slot, ks)                                               \
    do {                                                                        \
        _Pragma("unroll")                                                       \
        for (int mi = 0; mi < 4; ++mi)                                          \
            LDSM4(aF[buf] + mi * 4,                                             \
                  (slot) + A_OFF + aRow + (uint32_t)(mi * 2048) + xks[ks]);     \
        _Pragma("unroll")                                                       \
        for (int nb = 0; nb < 4; ++nb)                                          \
            LDSM4(bF[buf] + nb * 4,                                             \
                  (slot) + B_OFF + bRow + (uint32_t)(nb * 2048) + xks[ks]);     \
    } while (0)

#define DO_MMAS(buf)                                                            \
    do {                                                                        \
        _Pragma("unroll")                                                       \
        for (int mi = 0; mi < 4; ++mi) {                                        \
            _Pragma("unroll")                                                   \
            for (int j = 0; j < 8; ++j) {                                       \
                const int g = j >> 1, s = j & 1;                                \
                MMA16816(acc[mi][j], aF[buf] + mi * 4,                          \
                         bF[buf][g * 4 + s], bF[buf][g * 4 + 2 + s]);           \
            }                                                                   \
        }                                                                       \
    } while (0)

    for (int kt = 0; kt < NK; ++kt) {
        if (kt + 1 < NK) cp_wait1(); else cp_wait0();
        __syncthreads();

        if (kt + 2 < NK) {
            load_stage(sb + ((kt + 2) % STAGES) * SSIZE, kt + 2, tid, pA, pB);
            cp_commit();
        }

        const uint32_t slot = sb + (kt % STAGES) * SSIZE;

        // Software-pipelined k-steps: LDSM(ks+1) before MMA(ks)
        LOAD_FRAGS(0, slot, 0);
        LOAD_FRAGS(1, slot, 1);
        DO_MMAS(0);
        LOAD_FRAGS(0, slot, 2);
        DO_MMAS(1);
        LOAD_FRAGS(1, slot, 3);
        DO_MMAS(0);
        DO_MMAS(1);
    }

    // Epilogue: C frag (m16n8): c0,c1 at (m = l>>2, n = 2*(l&3)); c2,c3 at m+8.
    const int mBase = m0 + wm * 64;
    const int nBase = n0 + wn * 64;
    const int rsub  = lane >> 2;
    const int csub  = (lane & 3) * 2;
#pragma unroll
    for (int j = 0; j < 8; ++j) {
        const int n = nBase + j * 8 + csub;
        const float2 b2 = *reinterpret_cast<const float2*>(bias + n);
#pragma unroll
        for (int mi = 0; mi < 4; ++mi) {
            const int r0 = mBase + mi * 16 + rsub;
            float2 v0, v1;
            v0.x = acc[mi][j][0] + b2.x;
            v0.y = acc[mi][j][1] + b2.y;
            v1.x = acc[mi][j][2] + b2.x;
            v1.y = acc[mi][j][3] + b2.y;
            *reinterpret_cast<float2*>(out + (size_t)r0 * N_DIM + n)       = v0;
            *reinterpret_cast<float2*>(out + (size_t)(r0 + 8) * N_DIM + n) = v1;
        }
    }
}

// ---------------------------------------------------------------------------
// Entry point
// ---------------------------------------------------------------------------
extern "C" void kernel_launch(void* const* d_in, const int* in_sizes, int n_in,
                              void* d_out, int out_size) {
    const float* x    = (const float*)d_in[0];   // [4, 2048, 4096]
    const float* w    = (const float*)d_in[1];   // [4096, 4096]
    const float* bias = (const float*)d_in[2];   // [4096]
    const float* sw   = (const float*)d_in[3];   // [262144]
    const int*   idx  = (const int*)d_in[4];     // [2, 262144]
    float* out = (float*)d_out;                  // [8192, 4096]

    {
        const size_t n4 = (size_t)N_DIM * K_DIM / 4;
        convert_w_kernel<<<(int)((n4 + 255) / 256), 256>>>(w);
    }
    scatter_delta_kernel<<<(NNZ + 255) / 256, 256>>>(sw, idx);
    {
        const size_t n4 = (size_t)M_DIM * K_DIM / 4;
        convert_x_kernel<<<(int)((n4 + 255) / 256), 256>>>(x);
    }
    {
        cudaFuncSetAttribute(gemm_fp16_mma_kernel,
                             cudaFuncAttributeMaxDynamicSharedMemorySize, DSMEM_BYTES);
        dim3 grid(N_DIM / BN, M_DIM / BM);   // (32, 64)
        gemm_fp16_mma_kernel<<<grid, 128, DSMEM_BYTES>>>(bias, out);
    }
}